// round 1
// baseline (speedup 1.0000x reference)
#include <cuda_runtime.h>
#include <cuda_bf16.h>

// -----------------------------------------------------------------------------
// FrustumSegmentationNet — collapsed exact-math implementation.
//
// Key analysis (see theory): _fps_indices uses argmin over a non-negative
// distance array whose element 0 is exactly 0 -> every selected index is 0.
// Hence all 500 groups are identical, every row of `feats` is identical, and
// the dense-path batchnorms (axis 0, zero variance) squash everything:
//   feats = relu(be5) @ Wd3^T + bd3   (constant, independent of point data).
// The output therefore reduces to a 6->80 linear layer over the per-pixel
// point cloud plus a constant per-channel bias shift from feats.
// -----------------------------------------------------------------------------

#define HH 256
#define WW 256
#define HWPIX 65536
#define NCH 80
#define PIX 4

// Adjusted bias: adjB[c] = bs[c] + sum_j feats_const[j] * Ws[c, 6+j]
__device__ float g_adjB[NCH];

// ---- pre-kernel: compute constant feats vector and fold into bias ----------
__global__ void frustum_prep_kernel(const float* __restrict__ be5,   // (256)
                                    const float* __restrict__ Wd3,   // (128,256)
                                    const float* __restrict__ bd3,   // (128)
                                    const float* __restrict__ Ws,    // (80,134)
                                    const float* __restrict__ bs)    // (80)
{
    __shared__ float fc[128];
    int t = threadIdx.x;  // 128 threads
    // feats_const[t] = bd3[t] + sum_k relu(be5[k]) * Wd3[t,k]
    float s = bd3[t];
    #pragma unroll 8
    for (int k = 0; k < 256; k++)
        s += fmaxf(be5[k], 0.0f) * Wd3[t * 256 + k];
    fc[t] = s;
    __syncthreads();
    if (t < NCH) {
        float a = bs[t];
        #pragma unroll 8
        for (int j = 0; j < 128; j++)
            a += fc[j] * Ws[t * 134 + 6 + j];
        g_adjB[t] = a;
    }
}

// ---- main kernel: per-pixel point cloud + 6->80 linear, write full label ---
__global__ __launch_bounds__(128)
void frustum_seg_kernel(const float* __restrict__ rgb,    // (H,W,3)
                        const float* __restrict__ depth,  // (H,W)
                        const float* __restrict__ intr,   // (3,3)
                        const int*   __restrict__ box,    // (5)
                        const float* __restrict__ Ws,     // (80,134)
                        float* __restrict__ out)          // (80,H,W)
{
    __shared__ float sW[NCH * 6];
    __shared__ float sB[NCH];
    __shared__ float sK[9];
    __shared__ int   sbox[4];

    const int t = threadIdx.x;
    for (int i = t; i < NCH * 6; i += blockDim.x)
        sW[i] = Ws[(i / 6) * 134 + (i % 6)];
    if (t < NCH) sB[t] = g_adjB[t];
    if (t == 0) {
        // 3x3 inverse (adjugate / det)
        float a = intr[0], b = intr[1], c = intr[2];
        float d = intr[3], e = intr[4], f = intr[5];
        float g = intr[6], h = intr[7], i9 = intr[8];
        float det = a * (e * i9 - f * h) - b * (d * i9 - f * g) + c * (d * h - e * g);
        float inv = 1.0f / det;
        sK[0] = (e * i9 - f * h) * inv; sK[1] = (c * h - b * i9) * inv; sK[2] = (b * f - c * e) * inv;
        sK[3] = (f * g - d * i9) * inv; sK[4] = (a * i9 - c * g) * inv; sK[5] = (c * d - a * f) * inv;
        sK[6] = (d * h - e * g) * inv;  sK[7] = (b * g - a * h) * inv;  sK[8] = (a * e - b * d) * inv;
        sbox[0] = box[0]; sbox[1] = box[1]; sbox[2] = box[2]; sbox[3] = box[3];
    }
    __syncthreads();

    const int p0 = (blockIdx.x * blockDim.x + t) * PIX;
    if (p0 >= HWPIX) return;

    const int x1 = sbox[0], y1 = sbox[1], x2 = sbox[2], y2 = sbox[3];

    // vector loads: 4 depths, 12 rgb floats (both 16B aligned: p0 % 4 == 0)
    float4 dz = *reinterpret_cast<const float4*>(depth + p0);
    float zv[4] = {dz.x, dz.y, dz.z, dz.w};
    const float4* rp = reinterpret_cast<const float4*>(rgb + (size_t)p0 * 3);
    float4 r0 = rp[0], r1 = rp[1], r2 = rp[2];
    float rg[12] = {r0.x, r0.y, r0.z, r0.w, r1.x, r1.y, r1.z, r1.w,
                    r2.x, r2.y, r2.z, r2.w};

    float pc[PIX][6];
    bool  ins[PIX];
    #pragma unroll
    for (int i = 0; i < PIX; i++) {
        int p = p0 + i;
        int r = p >> 8;       // row (x index in reference)
        int cc = p & 255;     // col (y index)
        bool inside = (r >= x1) && (r < x2) && (cc >= y1) && (cc < y2);
        ins[i] = inside;
        float u = (float)(cc - y1) + 0.5f;
        float v = (float)(r - x1) + 0.5f;
        float z = zv[i];
        pc[i][0] = (sK[0] * u + sK[1] * v + sK[2]) * z;
        pc[i][1] = (sK[3] * u + sK[4] * v + sK[5]) * z;
        pc[i][2] = (sK[6] * u + sK[7] * v + sK[8]) * z;
        pc[i][3] = rg[i * 3 + 0];
        pc[i][4] = rg[i * 3 + 1];
        pc[i][5] = rg[i * 3 + 2];
    }

    #pragma unroll 4
    for (int c = 0; c < NCH; c++) {
        float w0 = sW[c * 6 + 0], w1 = sW[c * 6 + 1], w2 = sW[c * 6 + 2];
        float w3 = sW[c * 6 + 3], w4 = sW[c * 6 + 4], w5 = sW[c * 6 + 5];
        float bb = sB[c];
        float vals[PIX];
        #pragma unroll
        for (int i = 0; i < PIX; i++) {
            float s = bb;
            s = fmaf(w0, pc[i][0], s);
            s = fmaf(w1, pc[i][1], s);
            s = fmaf(w2, pc[i][2], s);
            s = fmaf(w3, pc[i][3], s);
            s = fmaf(w4, pc[i][4], s);
            s = fmaf(w5, pc[i][5], s);
            vals[i] = ins[i] ? s : 0.0f;
        }
        float4 o = {vals[0], vals[1], vals[2], vals[3]};
        *reinterpret_cast<float4*>(out + (size_t)c * HWPIX + p0) = o;
    }
}

// -----------------------------------------------------------------------------
// Input order (metadata): 0 rgb, 1 depth, 2 intrinsic, 3 box,
// 4..7 (W1,b1,g1,be1), 8..11 (W2..), 12..15 (W3..), 16..19 (Wd1,bd1,g4,be4),
// 20..23 (Wd2,bd2,g5,be5), 24 Wd3, 25 bd3, 26 Ws, 27 bs
// -----------------------------------------------------------------------------
extern "C" void kernel_launch(void* const* d_in, const int* in_sizes, int n_in,
                              void* d_out, int out_size)
{
    const float* rgb   = (const float*)d_in[0];
    const float* depth = (const float*)d_in[1];
    const float* intr  = (const float*)d_in[2];
    const int*   box   = (const int*)  d_in[3];
    const float* be5   = (const float*)d_in[23];
    const float* Wd3   = (const float*)d_in[24];
    const float* bd3   = (const float*)d_in[25];
    const float* Ws    = (const float*)d_in[26];
    const float* bs    = (const float*)d_in[27];
    float* out = (float*)d_out;

    frustum_prep_kernel<<<1, 128>>>(be5, Wd3, bd3, Ws, bs);
    frustum_seg_kernel<<<HWPIX / (PIX * 128), 128>>>(rgb, depth, intr, box, Ws, out);
}